// round 2
// baseline (speedup 1.0000x reference)
#include <cuda_runtime.h>
#include <cstdint>

// Problem constants
#define TB_   8192      // T*B = 128*64
#define N_J   24        // joints
#define D_    256       // input feature dim
#define H_    8         // heads
#define F_    32        // head dim
#define C3    768       // 3*H*F output cols of fused qkv gemm
#define HNF   6144      // H*N_J*F  (== N_J*D_ too)
#define ND    6144      // N_J*D_

// ---------------------------------------------------------------------------
// Scratch (allocation-free rule: __device__ globals)
// ---------------------------------------------------------------------------
__device__ float g_q[(size_t)TB_ * HNF];                 // [tb][h][n][f]
__device__ float g_k[(size_t)TB_ * HNF];
__device__ float g_v[(size_t)TB_ * HNF];
__device__ float g_bt[(size_t)N_J * D_ * C3];            // [n][d][c] packed weights

// ---------------------------------------------------------------------------
// Packed-f32x2 helpers (Blackwell fp32 runs 2x via f32x2 pipe)
// ---------------------------------------------------------------------------
__device__ __forceinline__ unsigned long long ffma2(unsigned long long a,
                                                    unsigned long long b,
                                                    unsigned long long c) {
    unsigned long long d;
    asm("fma.rn.f32x2 %0, %1, %2, %3;" : "=l"(d) : "l"(a), "l"(b), "l"(c));
    return d;
}
__device__ __forceinline__ unsigned long long pack_dup(float a) {
    unsigned long long d;
    asm("mov.b64 %0, {%1, %1};" : "=l"(d) : "f"(a));
    return d;
}
__device__ __forceinline__ void unpack2(unsigned long long p, float& lo, float& hi) {
    asm("mov.b64 {%0, %1}, %2;" : "=f"(lo), "=f"(hi) : "l"(p));
}

// ---------------------------------------------------------------------------
// Kernel 0: pack weights into k-major layout bt[n][d][c]
//   c in [0,256):   Wk[c][d]           (c = h*32+f)
//   c in [256,512): Wv[c-256][d]
//   c in [512,768): Wq[h][n][f][d]     (cq = c-512 = h*32+f)
// Threads: 73728 = 24 n * 768 c * 4 d-chunks. Lanes map to consecutive c so
// the scattered writes (stride C3 per d) coalesce across the warp; each lane
// streams 64 consecutive d on the read side (L1-friendly).
// ---------------------------------------------------------------------------
__global__ void pack_weights(const float* __restrict__ Wk,
                             const float* __restrict__ Wv,
                             const float* __restrict__ Wq) {
    int g = blockIdx.x * blockDim.x + threadIdx.x;   // 0..73727
    int c    = g % C3;
    int rest = g / C3;
    int n    = rest % N_J;
    int dc   = rest / N_J;                           // 0..3
    const float* src;
    if (c < 256) {
        src = Wk + (size_t)c * D_;
    } else if (c < 512) {
        src = Wv + (size_t)(c - 256) * D_;
    } else {
        int cq = c - 512;
        int h = cq >> 5, f = cq & 31;
        src = Wq + ((size_t)(h * N_J + n) * F_ + f) * D_;
    }
    float* dst = g_bt + (size_t)n * (D_ * C3) + c;
    int d0 = dc * 64;
#pragma unroll 4
    for (int d = d0; d < d0 + 64; d++)
        dst[(size_t)d * C3] = src[d];
}

// ---------------------------------------------------------------------------
// Kernel 1: fused QKV projection GEMM (per joint n).
//   C[m, c] = sum_d X[m0+m, n, d] * bt[n][d][c] + bias(c)   for c in [0,768)
// Tile 128x128, BK=8, 256 threads, 8x8 per thread (8 rows x 4 f32x2 pairs).
// smem double-buffered, one barrier per K-chunk. Epilogue scatters into the
// attention-friendly [tb][h][n][f] scratch layout with bias folded in.
// grid = (64 Mtiles, 6 Ntiles, 24 joints). Segment (k/v/q) = blockIdx.y/2.
// ---------------------------------------------------------------------------
__global__ void __launch_bounds__(256, 2)
qkv_gemm(const float* __restrict__ x,
         const float* __restrict__ bk,
         const float* __restrict__ bv,
         const float* __restrict__ bq) {
    __shared__ float As[2][8][128];
    __shared__ float Bs[2][8][128];

    const int tid = threadIdx.x;
    const int m0  = blockIdx.x * 128;
    const int c0  = blockIdx.y * 128;
    const int jn  = blockIdx.z;

    // loader mapping
    const int arow = tid >> 1;              // 0..127
    const int ak   = (tid & 1) * 4;         // 0 or 4
    const int bkr  = tid >> 5;              // 0..7   (k row of B tile)
    const int bcc  = (tid & 31) * 4;        // 0..124 (col of B tile)

    const float* aptr = x + (size_t)(m0 + arow) * ND + jn * D_ + ak;
    const float* bptr = g_bt + (size_t)jn * (D_ * C3) + (size_t)bkr * C3 + c0 + bcc;

    float4 aReg = *(const float4*)aptr;
    float4 bReg = *(const float4*)bptr;
    As[0][ak + 0][arow] = aReg.x;
    As[0][ak + 1][arow] = aReg.y;
    As[0][ak + 2][arow] = aReg.z;
    As[0][ak + 3][arow] = aReg.w;
    *(float4*)&Bs[0][bkr][bcc] = bReg;
    __syncthreads();

    const int ty = tid >> 4;                // 0..15 -> rows ty*8..+7
    const int tx = tid & 15;                // 0..15 -> cols tx*8..+7

    unsigned long long acc[8][4];
#pragma unroll
    for (int i = 0; i < 8; i++)
#pragma unroll
        for (int j = 0; j < 4; j++) acc[i][j] = 0ull;

    int cur = 0;
#pragma unroll 1
    for (int kk = 1; kk <= 32; kk++) {      // 256/8 = 32 K-chunks
        if (kk < 32) {
            aReg = *(const float4*)(aptr + kk * 8);
            bReg = *(const float4*)(bptr + (size_t)kk * 8 * C3);
        }
#pragma unroll
        for (int k = 0; k < 8; k++) {
            float4 a0 = *(const float4*)&As[cur][k][ty * 8];
            float4 a1 = *(const float4*)&As[cur][k][ty * 8 + 4];
            ulonglong2 bu0 = *(const ulonglong2*)&Bs[cur][k][tx * 8];
            ulonglong2 bu1 = *(const ulonglong2*)&Bs[cur][k][tx * 8 + 4];
            unsigned long long bp0 = bu0.x, bp1 = bu0.y, bp2 = bu1.x, bp3 = bu1.y;
            float av[8] = {a0.x, a0.y, a0.z, a0.w, a1.x, a1.y, a1.z, a1.w};
#pragma unroll
            for (int i = 0; i < 8; i++) {
                unsigned long long ap = pack_dup(av[i]);
                acc[i][0] = ffma2(ap, bp0, acc[i][0]);
                acc[i][1] = ffma2(ap, bp1, acc[i][1]);
                acc[i][2] = ffma2(ap, bp2, acc[i][2]);
                acc[i][3] = ffma2(ap, bp3, acc[i][3]);
            }
        }
        if (kk < 32) {
            int nxt = cur ^ 1;
            As[nxt][ak + 0][arow] = aReg.x;
            As[nxt][ak + 1][arow] = aReg.y;
            As[nxt][ak + 2][arow] = aReg.z;
            As[nxt][ak + 3][arow] = aReg.w;
            *(float4*)&Bs[nxt][bkr][bcc] = bReg;
            __syncthreads();
            cur = nxt;
        }
    }

    // Epilogue: segment is constant per block (Ntile 0,1->k; 2,3->v; 4,5->q)
    const int seg  = blockIdx.y >> 1;
    const int cseg = c0 - seg * 256 + tx * 8;     // 0..248, h constant over 8 cols
    const int h    = cseg >> 5;
    const int f    = cseg & 31;

    float* dstbase = (seg == 0) ? g_k : (seg == 1) ? g_v : g_q;

    float bias[8];
#pragma unroll
    for (int j = 0; j < 8; j++) {
        int cc = cseg + j;
        if (seg == 0)      bias[j] = __ldg(&bk[cc]);
        else if (seg == 1) bias[j] = __ldg(&bv[cc]);
        else               bias[j] = __ldg(&bq[(cc >> 5) * (N_J * F_) + jn * F_ + (cc & 31)]);
    }

    const size_t dstoff = (size_t)h * (N_J * F_) + jn * F_ + f;  // within-tb offset
#pragma unroll
    for (int i = 0; i < 8; i++) {
        int row = m0 + ty * 8 + i;
        float o[8];
#pragma unroll
        for (int j = 0; j < 4; j++) unpack2(acc[i][j], o[2 * j], o[2 * j + 1]);
#pragma unroll
        for (int j = 0; j < 8; j++) o[j] += bias[j];
        float* dp = dstbase + (size_t)row * HNF + dstoff;
        *(float4*)dp       = make_float4(o[0], o[1], o[2], o[3]);
        *(float4*)(dp + 4) = make_float4(o[4], o[5], o[6], o[7]);
    }
}

// ---------------------------------------------------------------------------
// Kernel 2: attention. One warp per (tb, h) unit; 8 warps per block.
// q,k,v (24x32 each) staged to smem (row stride 36 floats to dodge the
// 128B-stride bank aliasing), S = qk^T via 4x8 lane grid with 6x3 register
// tiles (f32x2 over the f axis), softmax by 24 lanes, O = P@V with 6x4 tiles.
// smem/warp = 3*24*36 + 24*25 = 3192 floats (12768 B); 8 warps -> 102144 B dyn.
// ---------------------------------------------------------------------------
#define WARP_SMEM 3192

__global__ void __launch_bounds__(256, 2)
attn_kernel(float* __restrict__ out) {
    extern __shared__ float sm[];
    const int wid  = threadIdx.x >> 5;
    const int lane = threadIdx.x & 31;
    const int unit = blockIdx.x * 8 + wid;
    const int tb = unit >> 3;
    const int h  = unit & 7;

    float* q = sm + wid * WARP_SMEM;        // 24 rows x stride 36
    float* k = q + 24 * 36;
    float* v = k + 24 * 36;
    float* p = v + 24 * 36;                 // 24 x stride 25

    const size_t base = (size_t)tb * HNF + (size_t)h * (N_J * F_);

    // Load q/k/v slabs (768 floats each, contiguous) into padded smem
#pragma unroll
    for (int t = 0; t < 6; t++) {
        int idx = lane + t * 32;            // float4 index 0..191
        int n   = idx >> 3;                 // 8 float4 per 32-float row
        int f   = (idx & 7) * 4;
        float4 vq = *(const float4*)(g_q + base + n * 32 + f);
        float4 vk = *(const float4*)(g_k + base + n * 32 + f);
        float4 vv = *(const float4*)(g_v + base + n * 32 + f);
        *(float4*)(q + n * 36 + f) = vq;
        *(float4*)(k + n * 36 + f) = vk;
        *(float4*)(v + n * 36 + f) = vv;
    }
    __syncwarp();

    const int r  = lane >> 3;               // 0..3  -> rows r*6..+5
    const int cg = lane & 7;                // 0..7  -> S cols cg*3..+2, O cols cg*4..+3

    // ---- S = q k^T (24x24, K=32), f32x2 over f pairs ----
    unsigned long long sp[6][3];
#pragma unroll
    for (int i = 0; i < 6; i++)
#pragma unroll
        for (int j = 0; j < 3; j++) sp[i][j] = 0ull;

#pragma unroll
    for (int f4 = 0; f4 < 8; f4++) {
        ulonglong2 kp[3];
#pragma unroll
        for (int j = 0; j < 3; j++)
            kp[j] = *(const ulonglong2*)(k + (cg * 3 + j) * 36 + f4 * 4);
#pragma unroll
        for (int i = 0; i < 6; i++) {
            ulonglong2 qp = *(const ulonglong2*)(q + (r * 6 + i) * 36 + f4 * 4);
#pragma unroll
            for (int j = 0; j < 3; j++) {
                sp[i][j] = ffma2(qp.x, kp[j].x, sp[i][j]);
                sp[i][j] = ffma2(qp.y, kp[j].y, sp[i][j]);
            }
        }
    }
#pragma unroll
    for (int i = 0; i < 6; i++)
#pragma unroll
        for (int j = 0; j < 3; j++) {
            float lo, hi;
            unpack2(sp[i][j], lo, hi);
            p[(r * 6 + i) * 25 + (cg * 3 + j)] = lo + hi;
        }
    __syncwarp();

    // ---- softmax over m, scaled by 1/sqrt(F) ----
    if (lane < 24) {
        const float SCALE = 0.17677669529663687f;   // 1/sqrt(32)
        float mx = -3.4e38f;
#pragma unroll
        for (int m = 0; m < 24; m++) mx = fmaxf(mx, p[lane * 25 + m]);
        float s = 0.f;
#pragma unroll
        for (int m = 0; m < 24; m++) {
            float e = __expf((p[lane * 25 + m] - mx) * SCALE);
            p[lane * 25 + m] = e;
            s += e;
        }
        float inv = 1.f / s;
#pragma unroll
        for (int m = 0; m < 24; m++) p[lane * 25 + m] *= inv;
    }
    __syncwarp();

    // ---- O = P @ V (24x32, K=24) ----
    unsigned long long op[6][2];
#pragma unroll
    for (int i = 0; i < 6; i++) { op[i][0] = 0ull; op[i][1] = 0ull; }

#pragma unroll
    for (int m = 0; m < 24; m++) {
        ulonglong2 vp = *(const ulonglong2*)(v + m * 36 + cg * 4);
#pragma unroll
        for (int i = 0; i < 6; i++) {
            unsigned long long pp = pack_dup(p[(r * 6 + i) * 25 + m]);
            op[i][0] = ffma2(pp, vp.x, op[i][0]);
            op[i][1] = ffma2(pp, vp.y, op[i][1]);
        }
    }

    // ---- write out[tb, n*256 + h*32 + f] ----
#pragma unroll
    for (int i = 0; i < 6; i++) {
        int n = r * 6 + i;
        float o0, o1, o2, o3;
        unpack2(op[i][0], o0, o1);
        unpack2(op[i][1], o2, o3);
        *(float4*)(out + (size_t)tb * HNF + n * 256 + h * 32 + cg * 4) =
            make_float4(o0, o1, o2, o3);
    }
}

// ---------------------------------------------------------------------------
// kernel_launch
// inputs: 0 inputs(T,B,N*D) 1 Wk(H,F,D) 2 bk(H,F) 3 Wv 4 bv 5 Wq(H,N,F,D) 6 bq(H,N,F)
// ---------------------------------------------------------------------------
extern "C" void kernel_launch(void* const* d_in, const int* in_sizes, int n_in,
                              void* d_out, int out_size) {
    const float* x  = (const float*)d_in[0];
    const float* Wk = (const float*)d_in[1];
    const float* bk = (const float*)d_in[2];
    const float* Wv = (const float*)d_in[3];
    const float* bv = (const float*)d_in[4];
    const float* Wq = (const float*)d_in[5];
    const float* bq = (const float*)d_in[6];
    float* out = (float*)d_out;

    // deterministic every call; capturable (host-side attribute set is immediate)
    cudaFuncSetAttribute(attn_kernel, cudaFuncAttributeMaxDynamicSharedMemorySize,
                         8 * WARP_SMEM * (int)sizeof(float));

    pack_weights<<<288, 256>>>(Wk, Wv, Wq);

    dim3 grid_g(64, 6, 24);
    qkv_gemm<<<grid_g, 256>>>(x, bk, bv, bq);

    attn_kernel<<<TB_ * H_ / 8, 256, 8 * WARP_SMEM * (int)sizeof(float)>>>(out);
}

// round 5
// speedup vs baseline: 1.6793x; 1.6793x over previous
#include <cuda_runtime.h>
#include <cuda_bf16.h>
#include <cstdint>

// ---------------------------------------------------------------------------
// Problem constants
// ---------------------------------------------------------------------------
#define TB_   8192      // T*B
#define N_J   24
#define D_    256
#define H_    8
#define F_    32
#define HNF   6144      // H*N_J*F == N_J*D_
#define ND    6144

// ---------------------------------------------------------------------------
// Scratch (__device__ globals; allocation-free rule)
// ---------------------------------------------------------------------------
__device__ float g_q[(size_t)TB_ * HNF];
__device__ float g_k[(size_t)TB_ * HNF];
__device__ float g_v[(size_t)TB_ * HNF];
__device__ __nv_bfloat16 g_wh[(size_t)N_J * 768 * 256];   // weight hi, [n][c][d]
__device__ __nv_bfloat16 g_wl[(size_t)N_J * 768 * 256];   // weight lo

// ---------------------------------------------------------------------------
// Helpers
// ---------------------------------------------------------------------------
__device__ __forceinline__ uint32_t smem_u32(const void* p) {
    uint32_t a;
    asm("{ .reg .u64 t; cvta.to.shared.u64 t, %1; cvt.u32.u64 %0, t; }" : "=r"(a) : "l"(p));
    return a;
}

__device__ __forceinline__ void ldsm_x4(uint32_t addr, uint32_t& r0, uint32_t& r1,
                                        uint32_t& r2, uint32_t& r3) {
    asm volatile("ldmatrix.sync.aligned.m8n8.x4.shared.b16 {%0,%1,%2,%3}, [%4];"
                 : "=r"(r0), "=r"(r1), "=r"(r2), "=r"(r3) : "r"(addr));
}

__device__ __forceinline__ void mma_bf16(float& d0, float& d1, float& d2, float& d3,
                                         uint32_t a0, uint32_t a1, uint32_t a2, uint32_t a3,
                                         uint32_t b0, uint32_t b1) {
    asm volatile(
        "mma.sync.aligned.m16n8k16.row.col.f32.bf16.bf16.f32 "
        "{%0,%1,%2,%3}, {%4,%5,%6,%7}, {%8,%9}, {%0,%1,%2,%3};"
        : "+f"(d0), "+f"(d1), "+f"(d2), "+f"(d3)
        : "r"(a0), "r"(a1), "r"(a2), "r"(a3), "r"(b0), "r"(b1));
}

__device__ __forceinline__ void cp_async16(uint32_t smem_dst, const void* gsrc) {
    asm volatile("cp.async.cg.shared.global [%0], [%1], 16;"
                 :: "r"(smem_dst), "l"(gsrc) : "memory");
}
#define CP_COMMIT() asm volatile("cp.async.commit_group;" ::: "memory")
#define CP_WAIT0()  asm volatile("cp.async.wait_group 0;" ::: "memory")

// f32x2 helpers (attention kernel)
__device__ __forceinline__ unsigned long long ffma2(unsigned long long a,
                                                    unsigned long long b,
                                                    unsigned long long c) {
    unsigned long long d;
    asm("fma.rn.f32x2 %0, %1, %2, %3;" : "=l"(d) : "l"(a), "l"(b), "l"(c));
    return d;
}
__device__ __forceinline__ unsigned long long pack_dup(float a) {
    unsigned long long d;
    asm("mov.b64 %0, {%1, %1};" : "=l"(d) : "f"(a));
    return d;
}
__device__ __forceinline__ void unpack2(unsigned long long p, float& lo, float& hi) {
    asm("mov.b64 {%0, %1}, %2;" : "=f"(lo), "=f"(hi) : "l"(p));
}

// split a float4 into bf16 hi quad + bf16 lo quad (packed 8B each)
__device__ __forceinline__ void split4(float4 f, uint2& hi, uint2& lo) {
    __nv_bfloat16 ha = __float2bfloat16(f.x), hb = __float2bfloat16(f.y);
    __nv_bfloat16 hc = __float2bfloat16(f.z), hd = __float2bfloat16(f.w);
    __nv_bfloat16 la = __float2bfloat16(f.x - __bfloat162float(ha));
    __nv_bfloat16 lb = __float2bfloat16(f.y - __bfloat162float(hb));
    __nv_bfloat16 lc = __float2bfloat16(f.z - __bfloat162float(hc));
    __nv_bfloat16 ld = __float2bfloat16(f.w - __bfloat162float(hd));
    hi.x = (uint32_t)__bfloat16_as_ushort(ha) | ((uint32_t)__bfloat16_as_ushort(hb) << 16);
    hi.y = (uint32_t)__bfloat16_as_ushort(hc) | ((uint32_t)__bfloat16_as_ushort(hd) << 16);
    lo.x = (uint32_t)__bfloat16_as_ushort(la) | ((uint32_t)__bfloat16_as_ushort(lb) << 16);
    lo.y = (uint32_t)__bfloat16_as_ushort(lc) | ((uint32_t)__bfloat16_as_ushort(ld) << 16);
}

// ---------------------------------------------------------------------------
// Kernel 0: split weights into bf16 hi/lo, gathered into [n][c(768)][d(256)]
// ---------------------------------------------------------------------------
__global__ void pack_w(const float* __restrict__ Wk,
                       const float* __restrict__ Wv,
                       const float* __restrict__ Wq) {
    int g = blockIdx.x * 256 + threadIdx.x;        // 0 .. 24*768*64-1
    int c4   = g & 63;
    int rest = g >> 6;
    int c    = rest % 768;
    int jn   = rest / 768;
    const float* src;
    if (c < 256)      src = Wk + (size_t)c * 256;
    else if (c < 512) src = Wv + (size_t)(c - 256) * 256;
    else {
        int cq = c - 512;
        src = Wq + ((size_t)((cq >> 5) * N_J + jn) * 32 + (cq & 31)) * 256;
    }
    float4 f = *(const float4*)(src + c4 * 4);
    uint2 hi, lo;
    split4(f, hi, lo);
    size_t dst = ((size_t)jn * 768 + c) * 256 + c4 * 4;
    *(uint2*)&g_wh[dst] = hi;
    *(uint2*)&g_wl[dst] = lo;
}

// ---------------------------------------------------------------------------
// Kernel 1: QKV GEMM via mma.sync bf16 (3-term split).
//   C[128, 128] per CTA; K = 256 in 4 chunks of 64.
//   grid = (6 ntiles, 64 mtiles, 24 joints). seg = ntile>>1 (k/v/q).
//   SMEM/stage: Ah, Al, Bh, Bl each 128 rows x 128 B (XOR-swizzled) = 64 KB;
//   2 stages = 128 KB. A loaded fp32 + split in regs; B via cp.async.
// ---------------------------------------------------------------------------
#define OFF_AH 0
#define OFF_AL 16384
#define OFF_BH 32768
#define OFF_BL 49152
#define STAGE_BYTES 65536
#define SMEM_GEMM (2 * STAGE_BYTES)

__global__ void __launch_bounds__(256, 1)
qkv_tc(const float* __restrict__ x,
       const float* __restrict__ bk,
       const float* __restrict__ bv,
       const float* __restrict__ bq) {
    extern __shared__ char smem[];
    const uint32_t sbase = smem_u32(smem);
    const int tid  = threadIdx.x;
    const int wid  = tid >> 5;
    const int lane = tid & 31;

    const int ntile = blockIdx.x;          // 0..5
    const int m0    = blockIdx.y * 128;
    const int jn    = blockIdx.z;
    const int c0    = ntile * 128;

    const int warp_m = (wid & 1) * 64;
    const int warp_n = (wid >> 1) * 32;

    const float* ap0 = x + (size_t)m0 * ND + jn * D_;
    const __nv_bfloat16* bh0 = g_wh + ((size_t)jn * 768 + c0) * 256;
    const __nv_bfloat16* bl0 = g_wl + ((size_t)jn * 768 + c0) * 256;

    // ---- B cp.async issue helper (8x 16B per thread per chunk) ----
    auto issueB = [&](int kc, uint32_t stg) {
#pragma unroll
        for (int i = 0; i < 4; i++) {
            int v  = tid + 256 * i;              // 0..1023
            int r  = v >> 3;                     // 0..127
            int cc = v & 7;
            uint32_t off = (uint32_t)(r * 128 + ((cc ^ (r & 7)) << 4));
            const char* sh = (const char*)(bh0 + (size_t)r * 256 + kc * 64 + cc * 8);
            const char* sl = (const char*)(bl0 + (size_t)r * 256 + kc * 64 + cc * 8);
            cp_async16(stg + OFF_BH + off, sh);
            cp_async16(stg + OFF_BL + off, sl);
        }
    };
    // ---- A load (fp32) into regs ----
    float4 apref[8];
    auto loadA = [&](int kc) {
#pragma unroll
        for (int i = 0; i < 8; i++) {
            int v  = tid + 256 * i;              // 0..2047
            int r  = v >> 4;                     // 0..127
            int c4 = v & 15;
            apref[i] = *(const float4*)(ap0 + (size_t)r * ND + kc * 64 + c4 * 4);
        }
    };
    // ---- A split + STS ----
    auto stsA = [&](uint32_t stg) {
#pragma unroll
        for (int i = 0; i < 8; i++) {
            int v  = tid + 256 * i;
            int r  = v >> 4;
            int c4 = v & 15;
            uint2 hi, lo;
            split4(apref[i], hi, lo);
            uint32_t off = (uint32_t)(r * 128 + (((c4 >> 1) ^ (r & 7)) << 4) + (c4 & 1) * 8);
            *(uint2*)(smem + (stg - sbase) + OFF_AH + off) = hi;
            *(uint2*)(smem + (stg - sbase) + OFF_AL + off) = lo;
        }
    };

    // accumulators: [mt][nt][4]
    float acc[4][4][4];
#pragma unroll
    for (int a = 0; a < 4; a++)
#pragma unroll
        for (int b = 0; b < 4; b++)
#pragma unroll
            for (int c = 0; c < 4; c++) acc[a][b][c] = 0.f;

    // per-lane fragment addressing constants
    const int lane15 = lane & 15;
    const int rm     = lane & 7;       // row & 7 (warp_m/warp_n multiples of 8)
    const int hi16   = lane >> 4;

    // prologue: chunk 0 into stage 0
    {
        uint32_t stg0 = sbase;
        issueB(0, stg0);
        CP_COMMIT();
        loadA(0);
        stsA(stg0);
        CP_WAIT0();
        __syncthreads();
    }

#pragma unroll 1
    for (int kc = 0; kc < 4; kc++) {
        uint32_t stg  = sbase + (kc & 1) * STAGE_BYTES;
        uint32_t nstg = sbase + ((kc + 1) & 1) * STAGE_BYTES;

        if (kc < 3) {
            issueB(kc + 1, nstg);
            CP_COMMIT();
            loadA(kc + 1);
        }

        // ---- compute chunk kc from stage stg ----
        const uint32_t AH = stg + OFF_AH, AL = stg + OFF_AL;
        const uint32_t BH = stg + OFF_BH, BL = stg + OFF_BL;
#pragma unroll
        for (int s = 0; s < 4; s++) {
            const int cc = s * 2 + hi16;
            uint32_t a[4][4], b[2][4];
            // term 1: Al * Bh
#pragma unroll
            for (int mt = 0; mt < 4; mt++) {
                int row = warp_m + mt * 16 + lane15;
                ldsm_x4(AL + row * 128 + ((cc ^ rm) << 4),
                        a[mt][0], a[mt][1], a[mt][2], a[mt][3]);
            }
#pragma unroll
            for (int u = 0; u < 2; u++) {
                int row = warp_n + u * 16 + lane15;
                ldsm_x4(BH + row * 128 + ((cc ^ rm) << 4),
                        b[u][0], b[u][1], b[u][2], b[u][3]);
            }
#pragma unroll
            for (int mt = 0; mt < 4; mt++)
#pragma unroll
                for (int nt = 0; nt < 4; nt++)
                    mma_bf16(acc[mt][nt][0], acc[mt][nt][1], acc[mt][nt][2], acc[mt][nt][3],
                             a[mt][0], a[mt][1], a[mt][2], a[mt][3],
                             b[nt >> 1][nt & 1], b[nt >> 1][2 + (nt & 1)]);
            // term 2: Ah * Bh  (reload A only)
#pragma unroll
            for (int mt = 0; mt < 4; mt++) {
                int row = warp_m + mt * 16 + lane15;
                ldsm_x4(AH + row * 128 + ((cc ^ rm) << 4),
                        a[mt][0], a[mt][1], a[mt][2], a[mt][3]);
            }
#pragma unroll
            for (int mt = 0; mt < 4; mt++)
#pragma unroll
                for (int nt = 0; nt < 4; nt++)
                    mma_bf16(acc[mt][nt][0], acc[mt][nt][1], acc[mt][nt][2], acc[mt][nt][3],
                             a[mt][0], a[mt][1], a[mt][2], a[mt][3],
                             b[nt >> 1][nt & 1], b[nt >> 1][2 + (nt & 1)]);
            // term 3: Ah * Bl  (reload B only)
#pragma unroll
            for (int u = 0; u < 2; u++) {
                int row = warp_n + u * 16 + lane15;
                ldsm_x4(BL + row * 128 + ((cc ^ rm) << 4),
                        b[u][0], b[u][1], b[u][2], b[u][3]);
            }
#pragma unroll
            for (int mt = 0; mt < 4; mt++)
#pragma unroll
                for (int nt = 0; nt < 4; nt++)
                    mma_bf16(acc[mt][nt][0], acc[mt][nt][1], acc[mt][nt][2], acc[mt][nt][3],
                             a[mt][0], a[mt][1], a[mt][2], a[mt][3],
                             b[nt >> 1][nt & 1], b[nt >> 1][2 + (nt & 1)]);
        }

        if (kc < 3) {
            stsA(nstg);
            CP_WAIT0();
        }
        __syncthreads();
    }

    // ---- epilogue: bias + scatter to g_k/g_v/g_q [tb][h][n][f] ----
    const int seg = ntile >> 1;
    float* dstbase = (seg == 0) ? g_k : (seg == 1) ? g_v : g_q;

#pragma unroll
    for (int nt = 0; nt < 4; nt++) {
        int n_local = warp_n + nt * 8 + (lane & 3) * 2;
        int cseg = c0 - seg * 256 + n_local;       // 0..254 (even)
        int h = cseg >> 5, f = cseg & 31;
        float b0, b1;
        if (seg == 0)      { b0 = __ldg(&bk[cseg]); b1 = __ldg(&bk[cseg + 1]); }
        else if (seg == 1) { b0 = __ldg(&bv[cseg]); b1 = __ldg(&bv[cseg + 1]); }
        else {
            b0 = __ldg(&bq[(size_t)h * 768 + jn * 32 + f]);
            b1 = __ldg(&bq[(size_t)h * 768 + jn * 32 + f + 1]);
        }
        size_t coloff = (size_t)h * 768 + jn * 32 + f;
#pragma unroll
        for (int mt = 0; mt < 4; mt++) {
            int row0 = m0 + warp_m + mt * 16 + (lane >> 2);
            float2 v0 = make_float2(acc[mt][nt][0] + b0, acc[mt][nt][1] + b1);
            float2 v1 = make_float2(acc[mt][nt][2] + b0, acc[mt][nt][3] + b1);
            *(float2*)(dstbase + (size_t)row0 * HNF + coloff) = v0;
            *(float2*)(dstbase + (size_t)(row0 + 8) * HNF + coloff) = v1;
        }
    }
}

// ---------------------------------------------------------------------------
// Kernel 2: attention (unchanged from passing round).
// ---------------------------------------------------------------------------
#define WARP_SMEM 3192

__global__ void __launch_bounds__(256, 2)
attn_kernel(float* __restrict__ out) {
    extern __shared__ float sm[];
    const int wid  = threadIdx.x >> 5;
    const int lane = threadIdx.x & 31;
    const int unit = blockIdx.x * 8 + wid;
    const int tb = unit >> 3;
    const int h  = unit & 7;

    float* q = sm + wid * WARP_SMEM;
    float* k = q + 24 * 36;
    float* v = k + 24 * 36;
    float* p = v + 24 * 36;

    const size_t base = (size_t)tb * HNF + (size_t)h * (N_J * F_);

#pragma unroll
    for (int t = 0; t < 6; t++) {
        int idx = lane + t * 32;
        int n   = idx >> 3;
        int f   = (idx & 7) * 4;
        float4 vq = *(const float4*)(g_q + base + n * 32 + f);
        float4 vk = *(const float4*)(g_k + base + n * 32 + f);
        float4 vv = *(const float4*)(g_v + base + n * 32 + f);
        *(float4*)(q + n * 36 + f) = vq;
        *(float4*)(k + n * 36 + f) = vk;
        *(float4*)(v + n * 36 + f) = vv;
    }
    __syncwarp();

    const int r  = lane >> 3;
    const int cg = lane & 7;

    unsigned long long sp[6][3];
#pragma unroll
    for (int i = 0; i < 6; i++)
#pragma unroll
        for (int j = 0; j < 3; j++) sp[i][j] = 0ull;

#pragma unroll
    for (int f4 = 0; f4 < 8; f4++) {
        ulonglong2 kp[3];
#pragma unroll
        for (int j = 0; j < 3; j++)
            kp[j] = *(const ulonglong2*)(k + (cg * 3 + j) * 36 + f4 * 4);
#pragma unroll
        for (int i = 0; i < 6; i++) {
            ulonglong2 qp = *(const ulonglong2*)(q + (r * 6 + i) * 36 + f4 * 4);
#pragma unroll
            for (int j = 0; j < 3; j++) {
                sp[i][j] = ffma2(qp.x, kp[j].x, sp[i][j]);
                sp[i][j] = ffma2(qp.y, kp[j].y, sp[i][j]);
            }
        }
    }
#pragma unroll
    for (int i = 0; i < 6; i++)
#pragma unroll
        for (int j = 0; j < 3; j++) {
            float lo, hi;
            unpack2(sp[i][j], lo, hi);
            p[(r * 6 + i) * 25 + (cg * 3 + j)] = lo + hi;
        }
    __syncwarp();

    if (lane < 24) {
        const float SCALE = 0.17677669529663687f;
        float mx = -3.4e38f;
#pragma unroll
        for (int m = 0; m < 24; m++) mx = fmaxf(mx, p[lane * 25 + m]);
        float s = 0.f;
#pragma unroll
        for (int m = 0; m < 24; m++) {
            float e = __expf((p[lane * 25 + m] - mx) * SCALE);
            p[lane * 25 + m] = e;
            s += e;
        }
        float inv = 1.f / s;
#pragma unroll
        for (int m = 0; m < 24; m++) p[lane * 25 + m] *= inv;
    }
    __syncwarp();

    unsigned long long op[6][2];
#pragma unroll
    for (int i = 0; i < 6; i++) { op[i][0] = 0ull; op[i][1] = 0ull; }

#pragma unroll
    for (int m = 0; m < 24; m++) {
        ulonglong2 vp = *(const ulonglong2*)(v + m * 36 + cg * 4);
#pragma unroll
        for (int i = 0; i < 6; i++) {
            unsigned long long pp = pack_dup(p[(r * 6 + i) * 25 + m]);
            op[i][0] = ffma2(pp, vp.x, op[i][0]);
            op[i][1] = ffma2(pp, vp.y, op[i][1]);
        }
    }

#pragma unroll
    for (int i = 0; i < 6; i++) {
        int n = r * 6 + i;
        float o0, o1, o2, o3;
        unpack2(op[i][0], o0, o1);
        unpack2(op[i][1], o2, o3);
        *(float4*)(out + (size_t)tb * HNF + n * 256 + h * 32 + cg * 4) =
            make_float4(o0, o1, o2, o3);
    }
}

// ---------------------------------------------------------------------------
// kernel_launch
// inputs: 0 x(T,B,N*D) 1 Wk(H,F,D) 2 bk(H,F) 3 Wv 4 bv 5 Wq(H,N,F,D) 6 bq(H,N,F)
// ---------------------------------------------------------------------------
extern "C" void kernel_launch(void* const* d_in, const int* in_sizes, int n_in,
                              void* d_out, int out_size) {
    const float* x  = (const float*)d_in[0];
    const float* Wk = (const float*)d_in[1];
    const float* bk = (const float*)d_in[2];
    const float* Wv = (const float*)d_in[3];
    const float* bv = (const float*)d_in[4];
    const float* Wq = (const float*)d_in[5];
    const float* bq = (const float*)d_in[6];
    float* out = (float*)d_out;

    cudaFuncSetAttribute(qkv_tc, cudaFuncAttributeMaxDynamicSharedMemorySize, SMEM_GEMM);
    cudaFuncSetAttribute(attn_kernel, cudaFuncAttributeMaxDynamicSharedMemorySize,
                         8 * WARP_SMEM * (int)sizeof(float));

    pack_w<<<4608, 256>>>(Wk, Wv, Wq);

    dim3 grid_g(6, 64, 24);
    qkv_tc<<<grid_g, 256, SMEM_GEMM>>>(x, bk, bv, bq);

    attn_kernel<<<TB_ * H_ / 8, 256, 8 * WARP_SMEM * (int)sizeof(float)>>>(out);
}

// round 6
// speedup vs baseline: 2.0049x; 1.1939x over previous
#include <cuda_runtime.h>
#include <cuda_bf16.h>
#include <cstdint>

// ---------------------------------------------------------------------------
// Problem constants
// ---------------------------------------------------------------------------
#define TB_   8192      // T*B
#define N_J   24
#define D_    256
#define H_    8
#define F_    32
#define HNF   6144      // H*N_J*F == N_J*D_
#define ND    6144

// ---------------------------------------------------------------------------
// Scratch (__device__ globals; allocation-free rule)
// ---------------------------------------------------------------------------
__device__ float g_q[(size_t)TB_ * HNF];
__device__ float g_k[(size_t)TB_ * HNF];
__device__ float g_v[(size_t)TB_ * HNF];
__device__ __nv_bfloat16 g_wh[(size_t)N_J * 768 * 256];   // weight hi, [n][c][d]
__device__ __nv_bfloat16 g_wl[(size_t)N_J * 768 * 256];   // weight lo

// ---------------------------------------------------------------------------
// Helpers
// ---------------------------------------------------------------------------
__device__ __forceinline__ uint32_t smem_u32(const void* p) {
    uint32_t a;
    asm("{ .reg .u64 t; cvta.to.shared.u64 t, %1; cvt.u32.u64 %0, t; }" : "=r"(a) : "l"(p));
    return a;
}

__device__ __forceinline__ void ldsm_x4(uint32_t addr, uint32_t& r0, uint32_t& r1,
                                        uint32_t& r2, uint32_t& r3) {
    asm volatile("ldmatrix.sync.aligned.m8n8.x4.shared.b16 {%0,%1,%2,%3}, [%4];"
                 : "=r"(r0), "=r"(r1), "=r"(r2), "=r"(r3) : "r"(addr));
}

__device__ __forceinline__ void mma_bf16(float& d0, float& d1, float& d2, float& d3,
                                         uint32_t a0, uint32_t a1, uint32_t a2, uint32_t a3,
                                         uint32_t b0, uint32_t b1) {
    asm volatile(
        "mma.sync.aligned.m16n8k16.row.col.f32.bf16.bf16.f32 "
        "{%0,%1,%2,%3}, {%4,%5,%6,%7}, {%8,%9}, {%0,%1,%2,%3};"
        : "+f"(d0), "+f"(d1), "+f"(d2), "+f"(d3)
        : "r"(a0), "r"(a1), "r"(a2), "r"(a3), "r"(b0), "r"(b1));
}

__device__ __forceinline__ void cp_async16(uint32_t smem_dst, const void* gsrc) {
    asm volatile("cp.async.cg.shared.global [%0], [%1], 16;"
                 :: "r"(smem_dst), "l"(gsrc) : "memory");
}
#define CP_COMMIT() asm volatile("cp.async.commit_group;" ::: "memory")
#define CP_WAIT0()  asm volatile("cp.async.wait_group 0;" ::: "memory")

// f32x2 helpers (attention kernel)
__device__ __forceinline__ unsigned long long ffma2(unsigned long long a,
                                                    unsigned long long b,
                                                    unsigned long long c) {
    unsigned long long d;
    asm("fma.rn.f32x2 %0, %1, %2, %3;" : "=l"(d) : "l"(a), "l"(b), "l"(c));
    return d;
}
__device__ __forceinline__ unsigned long long pack_dup(float a) {
    unsigned long long d;
    asm("mov.b64 %0, {%1, %1};" : "=l"(d) : "f"(a));
    return d;
}
__device__ __forceinline__ void unpack2(unsigned long long p, float& lo, float& hi) {
    asm("mov.b64 {%0, %1}, %2;" : "=f"(lo), "=f"(hi) : "l"(p));
}

// split a float4 into bf16 hi quad + bf16 lo quad (packed 8B each)
__device__ __forceinline__ void split4(float4 f, uint2& hi, uint2& lo) {
    __nv_bfloat16 ha = __float2bfloat16(f.x), hb = __float2bfloat16(f.y);
    __nv_bfloat16 hc = __float2bfloat16(f.z), hd = __float2bfloat16(f.w);
    __nv_bfloat16 la = __float2bfloat16(f.x - __bfloat162float(ha));
    __nv_bfloat16 lb = __float2bfloat16(f.y - __bfloat162float(hb));
    __nv_bfloat16 lc = __float2bfloat16(f.z - __bfloat162float(hc));
    __nv_bfloat16 ld = __float2bfloat16(f.w - __bfloat162float(hd));
    hi.x = (uint32_t)__bfloat16_as_ushort(ha) | ((uint32_t)__bfloat16_as_ushort(hb) << 16);
    hi.y = (uint32_t)__bfloat16_as_ushort(hc) | ((uint32_t)__bfloat16_as_ushort(hd) << 16);
    lo.x = (uint32_t)__bfloat16_as_ushort(la) | ((uint32_t)__bfloat16_as_ushort(lb) << 16);
    lo.y = (uint32_t)__bfloat16_as_ushort(lc) | ((uint32_t)__bfloat16_as_ushort(ld) << 16);
}

// ---------------------------------------------------------------------------
// Kernel 0: split weights into bf16 hi/lo, gathered into [n][c(768)][d(256)]
// ---------------------------------------------------------------------------
__global__ void pack_w(const float* __restrict__ Wk,
                       const float* __restrict__ Wv,
                       const float* __restrict__ Wq) {
    int g = blockIdx.x * 256 + threadIdx.x;        // 0 .. 24*768*64-1
    int c4   = g & 63;
    int rest = g >> 6;
    int c    = rest % 768;
    int jn   = rest / 768;
    const float* src;
    if (c < 256)      src = Wk + (size_t)c * 256;
    else if (c < 512) src = Wv + (size_t)(c - 256) * 256;
    else {
        int cq = c - 512;
        src = Wq + ((size_t)((cq >> 5) * N_J + jn) * 32 + (cq & 31)) * 256;
    }
    float4 f = *(const float4*)(src + c4 * 4);
    uint2 hi, lo;
    split4(f, hi, lo);
    size_t dst = ((size_t)jn * 768 + c) * 256 + c4 * 4;
    *(uint2*)&g_wh[dst] = hi;
    *(uint2*)&g_wl[dst] = lo;
}

// ---------------------------------------------------------------------------
// Kernel 1: QKV GEMM via mma.sync bf16 (3-term split).
//   C[128, 128] per CTA; K = 256 in 4 chunks of 64.
//   grid = (6 ntiles, 64 mtiles, 24 joints). seg = ntile>>1 (k/v/q).
//   SINGLE-stage smem (64 KB: Ah/Al/Bh/Bl 16 KB each) + 2 CTAs/SM:
//   co-resident CTAs provide the load/compute overlap (CTA-level double
//   buffering) instead of an in-CTA stage pair. Regs capped at 128 so both
//   CTAs fit the regfile (2*256*128 = 64K).
// ---------------------------------------------------------------------------
#define OFF_AH 0
#define OFF_AL 16384
#define OFF_BH 32768
#define OFF_BL 49152
#define SMEM_GEMM 65536

__global__ void __launch_bounds__(256, 2)
qkv_tc(const float* __restrict__ x,
       const float* __restrict__ bk,
       const float* __restrict__ bv,
       const float* __restrict__ bq) {
    extern __shared__ char smem[];
    const uint32_t sbase = smem_u32(smem);
    const int tid  = threadIdx.x;
    const int wid  = tid >> 5;
    const int lane = tid & 31;

    const int ntile = blockIdx.x;          // 0..5
    const int m0    = blockIdx.y * 128;
    const int jn    = blockIdx.z;
    const int c0    = ntile * 128;

    const int warp_m = (wid & 1) * 64;
    const int warp_n = (wid >> 1) * 32;

    const float* ap0 = x + (size_t)m0 * ND + jn * D_;
    const __nv_bfloat16* bh0 = g_wh + ((size_t)jn * 768 + c0) * 256;
    const __nv_bfloat16* bl0 = g_wl + ((size_t)jn * 768 + c0) * 256;

    // accumulators: [mt][nt][4]
    float acc[4][4][4];
#pragma unroll
    for (int a = 0; a < 4; a++)
#pragma unroll
        for (int b = 0; b < 4; b++)
#pragma unroll
            for (int c = 0; c < 4; c++) acc[a][b][c] = 0.f;

    // per-lane fragment addressing constants
    const int lane15 = lane & 15;
    const int rm     = lane & 7;       // row & 7 (warp_m/warp_n multiples of 8)
    const int hi16   = lane >> 4;

#pragma unroll 1
    for (int kc = 0; kc < 4; kc++) {
        if (kc > 0) __syncthreads();   // all warps done reading smem of prev chunk

        // ---- B tiles via cp.async (8x 16B per thread) ----
#pragma unroll
        for (int i = 0; i < 4; i++) {
            int v  = tid + 256 * i;              // 0..1023
            int r  = v >> 3;                     // 0..127
            int cc = v & 7;
            uint32_t off = (uint32_t)(r * 128 + ((cc ^ (r & 7)) << 4));
            const char* sh = (const char*)(bh0 + (size_t)r * 256 + kc * 64 + cc * 8);
            const char* sl = (const char*)(bl0 + (size_t)r * 256 + kc * 64 + cc * 8);
            cp_async16(sbase + OFF_BH + off, sh);
            cp_async16(sbase + OFF_BL + off, sl);
        }
        CP_COMMIT();

        // ---- A: load fp32, split to bf16 hi/lo, store swizzled ----
#pragma unroll
        for (int i = 0; i < 8; i++) {
            int v  = tid + 256 * i;              // 0..2047
            int r  = v >> 4;                     // 0..127
            int c4 = v & 15;
            float4 f = *(const float4*)(ap0 + (size_t)r * ND + kc * 64 + c4 * 4);
            uint2 hi, lo;
            split4(f, hi, lo);
            uint32_t off = (uint32_t)(r * 128 + (((c4 >> 1) ^ (r & 7)) << 4) + (c4 & 1) * 8);
            *(uint2*)(smem + OFF_AH + off) = hi;
            *(uint2*)(smem + OFF_AL + off) = lo;
        }

        CP_WAIT0();
        __syncthreads();

        // ---- compute chunk kc ----
        const uint32_t AH = sbase + OFF_AH, AL = sbase + OFF_AL;
        const uint32_t BH = sbase + OFF_BH, BL = sbase + OFF_BL;
#pragma unroll
        for (int s = 0; s < 4; s++) {
            const int cc = s * 2 + hi16;
            uint32_t a[4][4], b[2][4];
            // term 1: Al * Bh
#pragma unroll
            for (int mt = 0; mt < 4; mt++) {
                int row = warp_m + mt * 16 + lane15;
                ldsm_x4(AL + row * 128 + ((cc ^ rm) << 4),
                        a[mt][0], a[mt][1], a[mt][2], a[mt][3]);
            }
#pragma unroll
            for (int u = 0; u < 2; u++) {
                int row = warp_n + u * 16 + lane15;
                ldsm_x4(BH + row * 128 + ((cc ^ rm) << 4),
                        b[u][0], b[u][1], b[u][2], b[u][3]);
            }
#pragma unroll
            for (int mt = 0; mt < 4; mt++)
#pragma unroll
                for (int nt = 0; nt < 4; nt++)
                    mma_bf16(acc[mt][nt][0], acc[mt][nt][1], acc[mt][nt][2], acc[mt][nt][3],
                             a[mt][0], a[mt][1], a[mt][2], a[mt][3],
                             b[nt >> 1][nt & 1], b[nt >> 1][2 + (nt & 1)]);
            // term 2: Ah * Bh  (reload A only)
#pragma unroll
            for (int mt = 0; mt < 4; mt++) {
                int row = warp_m + mt * 16 + lane15;
                ldsm_x4(AH + row * 128 + ((cc ^ rm) << 4),
                        a[mt][0], a[mt][1], a[mt][2], a[mt][3]);
            }
#pragma unroll
            for (int mt = 0; mt < 4; mt++)
#pragma unroll
                for (int nt = 0; nt < 4; nt++)
                    mma_bf16(acc[mt][nt][0], acc[mt][nt][1], acc[mt][nt][2], acc[mt][nt][3],
                             a[mt][0], a[mt][1], a[mt][2], a[mt][3],
                             b[nt >> 1][nt & 1], b[nt >> 1][2 + (nt & 1)]);
            // term 3: Ah * Bl  (reload B only)
#pragma unroll
            for (int u = 0; u < 2; u++) {
                int row = warp_n + u * 16 + lane15;
                ldsm_x4(BL + row * 128 + ((cc ^ rm) << 4),
                        b[u][0], b[u][1], b[u][2], b[u][3]);
            }
#pragma unroll
            for (int mt = 0; mt < 4; mt++)
#pragma unroll
                for (int nt = 0; nt < 4; nt++)
                    mma_bf16(acc[mt][nt][0], acc[mt][nt][1], acc[mt][nt][2], acc[mt][nt][3],
                             a[mt][0], a[mt][1], a[mt][2], a[mt][3],
                             b[nt >> 1][nt & 1], b[nt >> 1][2 + (nt & 1)]);
        }
    }

    // ---- epilogue: bias + scatter to g_k/g_v/g_q [tb][h][n][f] ----
    const int seg = ntile >> 1;
    float* dstbase = (seg == 0) ? g_k : (seg == 1) ? g_v : g_q;

#pragma unroll
    for (int nt = 0; nt < 4; nt++) {
        int n_local = warp_n + nt * 8 + (lane & 3) * 2;
        int cseg = c0 - seg * 256 + n_local;       // 0..254 (even)
        int h = cseg >> 5, f = cseg & 31;
        float b0, b1;
        if (seg == 0)      { b0 = __ldg(&bk[cseg]); b1 = __ldg(&bk[cseg + 1]); }
        else if (seg == 1) { b0 = __ldg(&bv[cseg]); b1 = __ldg(&bv[cseg + 1]); }
        else {
            b0 = __ldg(&bq[(size_t)h * 768 + jn * 32 + f]);
            b1 = __ldg(&bq[(size_t)h * 768 + jn * 32 + f + 1]);
        }
        size_t coloff = (size_t)h * 768 + jn * 32 + f;
#pragma unroll
        for (int mt = 0; mt < 4; mt++) {
            int row0 = m0 + warp_m + mt * 16 + (lane >> 2);
            float2 v0 = make_float2(acc[mt][nt][0] + b0, acc[mt][nt][1] + b1);
            float2 v1 = make_float2(acc[mt][nt][2] + b0, acc[mt][nt][3] + b1);
            *(float2*)(dstbase + (size_t)row0 * HNF + coloff) = v0;
            *(float2*)(dstbase + (size_t)(row0 + 8) * HNF + coloff) = v1;
        }
    }
}

// ---------------------------------------------------------------------------
// Kernel 2: attention (unchanged from passing round).
// ---------------------------------------------------------------------------
#define WARP_SMEM 3192

__global__ void __launch_bounds__(256, 2)
attn_kernel(float* __restrict__ out) {
    extern __shared__ float sm[];
    const int wid  = threadIdx.x >> 5;
    const int lane = threadIdx.x & 31;
    const int unit = blockIdx.x * 8 + wid;
    const int tb = unit >> 3;
    const int h  = unit & 7;

    float* q = sm + wid * WARP_SMEM;
    float* k = q + 24 * 36;
    float* v = k + 24 * 36;
    float* p = v + 24 * 36;

    const size_t base = (size_t)tb * HNF + (size_t)h * (N_J * F_);

#pragma unroll
    for (int t = 0; t < 6; t++) {
        int idx = lane + t * 32;
        int n   = idx >> 3;
        int f   = (idx & 7) * 4;
        float4 vq = *(const float4*)(g_q + base + n * 32 + f);
        float4 vk = *(const float4*)(g_k + base + n * 32 + f);
        float4 vv = *(const float4*)(g_v + base + n * 32 + f);
        *(float4*)(q + n * 36 + f) = vq;
        *(float4*)(k + n * 36 + f) = vk;
        *(float4*)(v + n * 36 + f) = vv;
    }
    __syncwarp();

    const int r  = lane >> 3;
    const int cg = lane & 7;

    unsigned long long sp[6][3];
#pragma unroll
    for (int i = 0; i < 6; i++)
#pragma unroll
        for (int j = 0; j < 3; j++) sp[i][j] = 0ull;

#pragma unroll
    for (int f4 = 0; f4 < 8; f4++) {
        ulonglong2 kp[3];
#pragma unroll
        for (int j = 0; j < 3; j++)
            kp[j] = *(const ulonglong2*)(k + (cg * 3 + j) * 36 + f4 * 4);
#pragma unroll
        for (int i = 0; i < 6; i++) {
            ulonglong2 qp = *(const ulonglong2*)(q + (r * 6 + i) * 36 + f4 * 4);
#pragma unroll
            for (int j = 0; j < 3; j++) {
                sp[i][j] = ffma2(qp.x, kp[j].x, sp[i][j]);
                sp[i][j] = ffma2(qp.y, kp[j].y, sp[i][j]);
            }
        }
    }
#pragma unroll
    for (int i = 0; i < 6; i++)
#pragma unroll
        for (int j = 0; j < 3; j++) {
            float lo, hi;
            unpack2(sp[i][j], lo, hi);
            p[(r * 6 + i) * 25 + (cg * 3 + j)] = lo + hi;
        }
    __syncwarp();

    if (lane < 24) {
        const float SCALE = 0.17677669529663687f;
        float mx = -3.4e38f;
#pragma unroll
        for (int m = 0; m < 24; m++) mx = fmaxf(mx, p[lane * 25 + m]);
        float s = 0.f;
#pragma unroll
        for (int m = 0; m < 24; m++) {
            float e = __expf((p[lane * 25 + m] - mx) * SCALE);
            p[lane * 25 + m] = e;
            s += e;
        }
        float inv = 1.f / s;
#pragma unroll
        for (int m = 0; m < 24; m++) p[lane * 25 + m] *= inv;
    }
    __syncwarp();

    unsigned long long op[6][2];
#pragma unroll
    for (int i = 0; i < 6; i++) { op[i][0] = 0ull; op[i][1] = 0ull; }

#pragma unroll
    for (int m = 0; m < 24; m++) {
        ulonglong2 vp = *(const ulonglong2*)(v + m * 36 + cg * 4);
#pragma unroll
        for (int i = 0; i < 6; i++) {
            unsigned long long pp = pack_dup(p[(r * 6 + i) * 25 + m]);
            op[i][0] = ffma2(pp, vp.x, op[i][0]);
            op[i][1] = ffma2(pp, vp.y, op[i][1]);
        }
    }

#pragma unroll
    for (int i = 0; i < 6; i++) {
        int n = r * 6 + i;
        float o0, o1, o2, o3;
        unpack2(op[i][0], o0, o1);
        unpack2(op[i][1], o2, o3);
        *(float4*)(out + (size_t)tb * HNF + n * 256 + h * 32 + cg * 4) =
            make_float4(o0, o1, o2, o3);
    }
}

// ---------------------------------------------------------------------------
// kernel_launch
// inputs: 0 x(T,B,N*D) 1 Wk(H,F,D) 2 bk(H,F) 3 Wv 4 bv 5 Wq(H,N,F,D) 6 bq(H,N,F)
// ---------------------------------------------------------------------------
extern "C" void kernel_launch(void* const* d_in, const int* in_sizes, int n_in,
                              void* d_out, int out_size) {
    const float* x  = (const float*)d_in[0];
    const float* Wk = (const float*)d_in[1];
    const float* bk = (const float*)d_in[2];
    const float* Wv = (const float*)d_in[3];
    const float* bv = (const float*)d_in[4];
    const float* Wq = (const float*)d_in[5];
    const float* bq = (const float*)d_in[6];
    float* out = (float*)d_out;

    cudaFuncSetAttribute(qkv_tc, cudaFuncAttributeMaxDynamicSharedMemorySize, SMEM_GEMM);
    cudaFuncSetAttribute(attn_kernel, cudaFuncAttributeMaxDynamicSharedMemorySize,
                         8 * WARP_SMEM * (int)sizeof(float));

    pack_w<<<4608, 256>>>(Wk, Wv, Wq);

    dim3 grid_g(6, 64, 24);
    qkv_tc<<<grid_g, 256, SMEM_GEMM>>>(x, bk, bv, bq);

    attn_kernel<<<TB_ * H_ / 8, 256, 8 * WARP_SMEM * (int)sizeof(float)>>>(out);
}